// round 5
// baseline (speedup 1.0000x reference)
#include <cuda_runtime.h>
#include <cuda_bf16.h>

// ---------------- problem constants ----------------
#define NNODES 100000
#define NEDGES 1600000
#define IND    128
#define HD     64
#define EDD    64
#define NLAYER 3
#define OUTD   3

#define TE     256            // edges per tile
#define NTHR   256            // threads per block (8 warps)
#define NTILES (NEDGES / TE)  // 6250

// ---------------- device scratch (static globals; no allocations) ----------------
__device__ float g_h  [(size_t)NNODES * HD];    // node features
__device__ float g_agg[(size_t)NNODES * HD];    // scatter accumulator
__device__ float g_ea [(size_t)NEDGES * EDD];   // edge features between layers
__device__ float g_pool[HD];                    // pooled sums

// ---------------- f32x2 helpers ----------------
#define FMA2(acc, a, b) \
    asm("fma.rn.f32x2 %0, %1, %2, %0;" : "+l"(acc) : "l"(a), "l"(b))
#define PACK2(d, x, y) \
    asm("mov.b64 %0, {%1, %2};" : "=l"(d) : "f"(x), "f"(y))
#define DUP2(d, x) \
    asm("mov.b64 %0, {%1, %1};" : "=l"(d) : "f"(x))
#define UNPACK2(x, y, d) \
    asm("mov.b64 {%0, %1}, %2;" : "=f"(x), "=f"(y) : "l"(d))

typedef unsigned long long ull;

// ---------------- smem carve (floats) ----------------
// B1 [64][256]  @ 0       (h[row])
// B2 [64][256]  @ 16384   (h[col] -> EA')
// B3 [64][256]  @ 32768   (EA -> T -> T2)
// sW [64][64]   @ 49152   (4096 floats, one weight chunk)
// idx           @ 53248   (512 ints)
#define OFF_B1  0
#define OFF_B2  16384
#define OFF_B3  32768
#define OFF_W   49152
#define OFF_IDX 53248
#define SMEM_EDGE_FLOATS (OFF_IDX + 512)
#define SMEM_EDGE_BYTES  (SMEM_EDGE_FLOATS * 4)   // 215,040 B

// stage one 64x64 weight chunk (4096 floats)
__device__ __forceinline__ void stage_w(const float* __restrict__ g, float* __restrict__ s,
                                        int tid) {
    const float4* gs = (const float4*)g;
    float4* ss = (float4*)s;
#pragma unroll
    for (int i = 0; i < 4; i++) ss[tid + i * NTHR] = gs[tid + i * NTHR];
}

// thread-per-edge gather: 64 consecutive floats -> k-major column (stride TE)
__device__ __forceinline__ void gather_full(const float* __restrict__ src,
                                            float* __restrict__ dst) {
#pragma unroll
    for (int i = 0; i < 16; i++) {
        float4 v = ((const float4*)src)[i];
        dst[(4 * i + 0) * TE] = v.x;
        dst[(4 * i + 1) * TE] = v.y;
        dst[(4 * i + 2) * TE] = v.z;
        dst[(4 * i + 3) * TE] = v.w;
    }
}

// acc[e][p]: 4 edges x 8 out-pairs (16 outs starting at wo)
__device__ __forceinline__ void init_acc(ull acc[4][8], const float* __restrict__ bias,
                                         int wo) {
    float4 b0 = *(const float4*)(bias + wo);
    float4 b1 = *(const float4*)(bias + wo + 4);
    float4 b2 = *(const float4*)(bias + wo + 8);
    float4 b3 = *(const float4*)(bias + wo + 12);
    ull bb[8];
    PACK2(bb[0], b0.x, b0.y); PACK2(bb[1], b0.z, b0.w);
    PACK2(bb[2], b1.x, b1.y); PACK2(bb[3], b1.z, b1.w);
    PACK2(bb[4], b2.x, b2.y); PACK2(bb[5], b2.z, b2.w);
    PACK2(bb[6], b3.x, b3.y); PACK2(bb[7], b3.z, b3.w);
#pragma unroll
    for (int e = 0; e < 4; e++)
#pragma unroll
        for (int p = 0; p < 8; p++) acc[e][p] = bb[p];
}

// one 64-k chunk: acc[e][p] += A[k][edge] * W[k][out]
__device__ __forceinline__ void accum64(const float* __restrict__ sA,
                                        const float* __restrict__ sWc,
                                        int a_off, int wo, ull acc[4][8]) {
#pragma unroll 2
    for (int k = 0; k < 64; k++) {
        float4 av = *(const float4*)(sA + k * TE + a_off);
        const float* wr = sWc + k * 64 + wo;
        ulonglong2 wa = *(const ulonglong2*)(wr);
        ulonglong2 wb = *(const ulonglong2*)(wr + 4);
        ulonglong2 wc = *(const ulonglong2*)(wr + 8);
        ulonglong2 wd = *(const ulonglong2*)(wr + 12);
        ull w[8] = {wa.x, wa.y, wb.x, wb.y, wc.x, wc.y, wd.x, wd.y};
        ull d[4];
        DUP2(d[0], av.x); DUP2(d[1], av.y); DUP2(d[2], av.z); DUP2(d[3], av.w);
#pragma unroll
        for (int e = 0; e < 4; e++)
#pragma unroll
            for (int p = 0; p < 8; p++) FMA2(acc[e][p], d[e], w[p]);
    }
}

template <bool RELU>
__device__ __forceinline__ void epilogue_store(ull acc[4][8], float* __restrict__ sDst,
                                               int a_off, int wo) {
#pragma unroll
    for (int p = 0; p < 8; p++) {
        float lo[4], hi[4];
#pragma unroll
        for (int e = 0; e < 4; e++) {
            UNPACK2(lo[e], hi[e], acc[e][p]);
            if (RELU) { lo[e] = fmaxf(lo[e], 0.f); hi[e] = fmaxf(hi[e], 0.f); }
        }
        *(float4*)(sDst + (wo + 2 * p + 0) * TE + a_off) = make_float4(lo[0], lo[1], lo[2], lo[3]);
        *(float4*)(sDst + (wo + 2 * p + 1) * TE + a_off) = make_float4(hi[0], hi[1], hi[2], hi[3]);
    }
}

__device__ __forceinline__ void red_v4(float* p, float a, float b, float c, float d) {
    asm volatile("red.global.add.v4.f32 [%0], {%1, %2, %3, %4};"
                 :: "l"(p), "f"(a), "f"(b), "f"(c), "f"(d) : "memory");
}

__global__ void __launch_bounds__(NTHR, 1)
edge_kernel(const int* __restrict__ ei, const float* __restrict__ ea_in,
            const float* __restrict__ W1, const float* __restrict__ B1b,
            const float* __restrict__ W2, const float* __restrict__ B2b,
            const float* __restrict__ W3, const float* __restrict__ B3b,
            const float* __restrict__ W4, const float* __restrict__ B4b,
            int write_ea) {
    extern __shared__ float sm[];
    float* bHrow = sm + OFF_B1;   // h[row]          (read-only all layers)
    float* bAux  = sm + OFF_B2;   // h[col] -> EA'
    float* bMain = sm + OFF_B3;   // EA -> T -> T2
    float* sW    = sm + OFF_W;
    int*   sRow  = (int*)(sm + OFF_IDX);
    int*   sCol  = sRow + TE;

    const int tid   = threadIdx.x;
    const int lane  = tid & 31;
    const int wid   = tid >> 5;
    const int o_sub = lane >> 3;         // 0..3 -> out group of 16
    const int e_sub = lane & 7;          // 0..7 -> 4-edge group within warp
    const int a_off = wid * 32 + e_sub * 4;  // first edge of this thread
    const int wo    = o_sub * 16;            // first out of this thread
    const long long e0 = (long long)blockIdx.x * TE;

    sRow[tid] = ei[e0 + tid];
    sCol[tid] = ei[(long long)NEDGES + e0 + tid];
    __syncthreads();

    // gathers: thread t owns edge t (conflict-free STS, 1 phase/instr)
    {
        int r = sRow[tid], c = sCol[tid];
        gather_full(g_h + (size_t)r * HD, bHrow + tid);
        gather_full(g_h + (size_t)c * HD, bAux + tid);
        gather_full(ea_in + (size_t)(e0 + tid) * EDD, bMain + tid);
    }
    stage_w(W1, sW, tid);
    __syncthreads();

    ull acc[4][8];

    // ---- GEMM1: relu([hrow, hcol, ea] @ W1 + b1) -> bMain (T) ----
    init_acc(acc, B1b, wo);
    accum64(bHrow, sW, a_off, wo, acc);
    __syncthreads();
    stage_w(W1 + 64 * 64, sW, tid);
    __syncthreads();
    accum64(bAux, sW, a_off, wo, acc);
    __syncthreads();
    stage_w(W1 + 128 * 64, sW, tid);
    __syncthreads();
    accum64(bMain, sW, a_off, wo, acc);
    __syncthreads();                       // all bMain reads done
    epilogue_store<true>(acc, bMain, a_off, wo);
    stage_w(W2, sW, tid);
    __syncthreads();

    // ---- GEMM2: T @ W2 + b2 -> bAux (EA') ----
    init_acc(acc, B2b, wo);
    accum64(bMain, sW, a_off, wo, acc);
    __syncthreads();                       // all bAux reads (GEMM1) + sW reads done
    epilogue_store<false>(acc, bAux, a_off, wo);
    stage_w(W3, sW, tid);
    __syncthreads();

    // ---- GEMM3: relu([hrow, EA'] @ W3 + b3) -> bMain (T2) ----
    init_acc(acc, B3b, wo);
    accum64(bHrow, sW, a_off, wo, acc);
    __syncthreads();
    stage_w(W3 + 64 * 64, sW, tid);
    __syncthreads();
    accum64(bAux, sW, a_off, wo, acc);
    __syncthreads();                       // bMain reads (GEMM2) long done
    epilogue_store<true>(acc, bMain, a_off, wo);
    stage_w(W4, sW, tid);
    __syncthreads();

    // ---- GEMM4: msg = T2 @ W4 + b4 -> scatter-add into g_agg[col] ----
    init_acc(acc, B4b, wo);
    accum64(bMain, sW, a_off, wo, acc);

#pragma unroll
    for (int e = 0; e < 4; e++) {
        float v[16];
#pragma unroll
        for (int p = 0; p < 8; p++) UNPACK2(v[2 * p], v[2 * p + 1], acc[e][p]);
        int c = sCol[a_off + e];
        float* p = g_agg + (size_t)c * HD + wo;
        red_v4(p,      v[0],  v[1],  v[2],  v[3]);
        red_v4(p + 4,  v[4],  v[5],  v[6],  v[7]);
        red_v4(p + 8,  v[8],  v[9],  v[10], v[11]);
        red_v4(p + 12, v[12], v[13], v[14], v[15]);
    }

    // persist EA' for next layer (thread t = edge t; coalesced STG.128)
    if (write_ea) {
        const float* src = bAux + tid;
        float4* dst = (float4*)(g_ea + (size_t)(e0 + tid) * EDD);
#pragma unroll
        for (int i = 0; i < 16; i++) {
            float4 w;
            w.x = src[(4 * i + 0) * TE];
            w.y = src[(4 * i + 1) * TE];
            w.z = src[(4 * i + 2) * TE];
            w.w = src[(4 * i + 3) * TE];
            dst[i] = w;
        }
    }
}

// ---------------- node projection: h = x @ pW + pb ; agg = 0 ----------------
#define SMEM_PROJ_FLOATS (32 * 132 + 128 * 64)
#define SMEM_PROJ_BYTES  (SMEM_PROJ_FLOATS * 4)

__global__ void __launch_bounds__(NTHR, 1)
proj_kernel(const float* __restrict__ x, const float* __restrict__ pW,
            const float* __restrict__ pb) {
    extern __shared__ float sm[];
    float* xs  = sm;            // [32][132]
    float* sWp = sm + 32 * 132; // [128][64]
    int tid = threadIdx.x;
    int nb0 = blockIdx.x * 32;

    {
        const float4* gx = (const float4*)(x + (size_t)nb0 * IND);
        for (int i = tid; i < 1024; i += NTHR) {
            float4 vv = gx[i];
            *(float4*)(xs + (i >> 5) * 132 + ((i & 31) << 2)) = vv;
        }
    }
    {
        const float4* gw = (const float4*)pW;
        float4* sw = (float4*)sWp;
        for (int i = tid; i < 2048; i += NTHR) sw[i] = gw[i];
    }
    __syncthreads();

    int node = tid >> 3, g = tid & 7;
    float a0[8];
    float4 b0 = *(const float4*)(pb + 8 * g);
    float4 b1 = *(const float4*)(pb + 8 * g + 4);
    a0[0] = b0.x; a0[1] = b0.y; a0[2] = b0.z; a0[3] = b0.w;
    a0[4] = b1.x; a0[5] = b1.y; a0[6] = b1.z; a0[7] = b1.w;
#pragma unroll 4
    for (int k = 0; k < IND; k++) {
        float a = xs[node * 132 + k];
        float4 w0 = *(const float4*)(sWp + k * 64 + 8 * g);
        float4 w1 = *(const float4*)(sWp + k * 64 + 8 * g + 4);
        a0[0] = fmaf(a, w0.x, a0[0]); a0[1] = fmaf(a, w0.y, a0[1]);
        a0[2] = fmaf(a, w0.z, a0[2]); a0[3] = fmaf(a, w0.w, a0[3]);
        a0[4] = fmaf(a, w1.x, a0[4]); a0[5] = fmaf(a, w1.y, a0[5]);
        a0[6] = fmaf(a, w1.z, a0[6]); a0[7] = fmaf(a, w1.w, a0[7]);
    }
    size_t base = (size_t)(nb0 + node) * HD + 8 * g;
    *(float4*)(g_h + base)     = make_float4(a0[0], a0[1], a0[2], a0[3]);
    *(float4*)(g_h + base + 4) = make_float4(a0[4], a0[5], a0[6], a0[7]);
    *(float4*)(g_agg + base)     = make_float4(0.f, 0.f, 0.f, 0.f);
    *(float4*)(g_agg + base + 4) = make_float4(0.f, 0.f, 0.f, 0.f);
}

// ---------------- node update: h = relu(agg + h); agg = 0; zero g_pool ----------------
__global__ void node_update_kernel() {
    size_t i = (size_t)blockIdx.x * NTHR + threadIdx.x;  // float4 index
    float4* h4 = (float4*)g_h;
    float4* a4 = (float4*)g_agg;
    float4 h = h4[i], a = a4[i];
    h.x = fmaxf(h.x + a.x, 0.f);
    h.y = fmaxf(h.y + a.y, 0.f);
    h.z = fmaxf(h.z + a.z, 0.f);
    h.w = fmaxf(h.w + a.w, 0.f);
    h4[i] = h;
    a4[i] = make_float4(0.f, 0.f, 0.f, 0.f);
    if (blockIdx.x == 0 && threadIdx.x < HD) g_pool[threadIdx.x] = 0.f;
}

// ---------------- pooling ----------------
__global__ void pool_kernel() {
    __shared__ float sP[NTHR];
    int tid = threadIdx.x;
    int k = tid & 63, sub = tid >> 6;
    int n0 = blockIdx.x * 256 + sub * 64;
    float s = 0.f;
#pragma unroll 4
    for (int i = 0; i < 64; i++) {
        int n = n0 + i;
        if (n < NNODES) s += g_h[(size_t)n * HD + k];
    }
    sP[tid] = s;
    __syncthreads();
    if (tid < 64) {
        float t = sP[tid] + sP[tid + 64] + sP[tid + 128] + sP[tid + 192];
        atomicAdd(&g_pool[tid], t);
    }
}

// ---------------- final ----------------
__global__ void final_kernel(const float* __restrict__ lW, const float* __restrict__ lb,
                             float* __restrict__ out) {
    int o = threadIdx.x;
    if (o < OUTD) {
        const float invN = 1.0f / (float)NNODES;
        float s = lb[o];
        for (int k = 0; k < HD; k++) s = fmaf(g_pool[k] * invN, lW[k * OUTD + o], s);
        out[o] = s;
    }
}

// ---------------- launch ----------------
extern "C" void kernel_launch(void* const* d_in, const int* in_sizes, int n_in,
                              void* d_out, int out_size) {
    const float* x   = (const float*)d_in[0];
    const int*   ei  = (const int*)d_in[1];       // int32 (JAX x64 disabled)
    const float* ea  = (const float*)d_in[2];
    const float* pW  = (const float*)d_in[3];
    const float* pb  = (const float*)d_in[4];
    const float* eW1 = (const float*)d_in[5];
    const float* eb1 = (const float*)d_in[6];
    const float* eW2 = (const float*)d_in[7];
    const float* eb2 = (const float*)d_in[8];
    const float* nW1 = (const float*)d_in[9];
    const float* nb1 = (const float*)d_in[10];
    const float* nW2 = (const float*)d_in[11];
    const float* nb2 = (const float*)d_in[12];
    const float* lW  = (const float*)d_in[13];
    const float* lb  = (const float*)d_in[14];
    float* out = (float*)d_out;

    cudaFuncSetAttribute(edge_kernel, cudaFuncAttributeMaxDynamicSharedMemorySize, SMEM_EDGE_BYTES);
    cudaFuncSetAttribute(proj_kernel, cudaFuncAttributeMaxDynamicSharedMemorySize, SMEM_PROJ_BYTES);

    float* g_ea_ptr;
    cudaGetSymbolAddress((void**)&g_ea_ptr, g_ea);

    proj_kernel<<<NNODES / 32, NTHR, SMEM_PROJ_BYTES>>>(x, pW, pb);

    for (int l = 0; l < NLAYER; l++) {
        const float* ea_in = (l == 0) ? ea : (const float*)g_ea_ptr;
        edge_kernel<<<NTILES, NTHR, SMEM_EDGE_BYTES>>>(
            ei, ea_in,
            eW1 + (size_t)l * 192 * 64, eb1 + l * 64,
            eW2 + (size_t)l * 64 * 64,  eb2 + l * 64,
            nW1 + (size_t)l * 128 * 64, nb1 + l * 64,
            nW2 + (size_t)l * 64 * 64,  nb2 + l * 64,
            (l < NLAYER - 1) ? 1 : 0);
        node_update_kernel<<<(NNODES * HD) / (4 * NTHR), NTHR>>>();
    }

    pool_kernel<<<(NNODES + 255) / 256, NTHR>>>();
    final_kernel<<<1, 32>>>(lW, lb, out);
}